// round 13
// baseline (speedup 1.0000x reference)
#include <cuda_runtime.h>
#include <cuda_bf16.h>
#include <math.h>
#include <stdint.h>

// Problem constants
#define Bq  4
#define Nn  8192
#define Cc  256
#define Ee  262144
#define NC  (Nn * Cc)
#define Mtot (Bq * Nn)          // 32768 GEMM rows

// ---------------------------------------------------------------------------
// helpers (plain sm_103-safe ISA: cp.async / ldmatrix / mma.sync)
// ---------------------------------------------------------------------------
__device__ __forceinline__ uint32_t smem_u32(const void* p) {
    uint32_t a;
    asm("{ .reg .u64 t; cvta.to.shared.u64 t, %1; cvt.u32.u64 %0, t; }"
        : "=r"(a) : "l"(p));
    return a;
}
#define CP_ASYNC16(dst, src) \
    asm volatile("cp.async.cg.shared.global [%0], [%1], 16;" :: "r"(dst), "l"(src))
#define CP_COMMIT() asm volatile("cp.async.commit_group;" ::: "memory")
#define CP_WAIT1()  asm volatile("cp.async.wait_group 1;" ::: "memory")
#define CP_WAIT0()  asm volatile("cp.async.wait_group 0;" ::: "memory")
#define LDSM_X4(r0, r1, r2, r3, a) \
    asm volatile("ldmatrix.sync.aligned.m8n8.x4.shared.b16 {%0,%1,%2,%3}, [%4];" \
                 : "=r"(r0), "=r"(r1), "=r"(r2), "=r"(r3) : "r"(a))
#define MMA_BF16(c, a, b0, b1) \
    asm volatile("mma.sync.aligned.m16n8k16.row.col.f32.bf16.bf16.f32 " \
                 "{%0,%1,%2,%3}, {%4,%5,%6,%7}, {%8,%9}, {%0,%1,%2,%3};" \
                 : "+f"((c)[0]), "+f"((c)[1]), "+f"((c)[2]), "+f"((c)[3]) \
                 : "r"((a)[0]), "r"((a)[1]), "r"((a)[2]), "r"((a)[3]), \
                   "r"(b0), "r"(b1))

__device__ __forceinline__ float gelu_f(float h) {
    return 0.5f * h * (1.0f + erff(h * 0.70710678118654752f));
}

// ---------------- scratch (static device globals — no allocation) -----------
__device__ int   g_deg[Nn];
__device__ int   g_cur[Nn];
__device__ int   g_off[Nn + 1];
__device__ float g_invdeg[Nn];
__device__ int   g_col[Ee];
__device__ int   g_is64;
__device__ __align__(16) __nv_bfloat16 g_xh[Mtot * Cc];
__device__ __align__(16) __nv_bfloat16 g_xl[Mtot * Cc];
__device__ __align__(16) __nv_bfloat16 g_ah[Mtot * Cc];
__device__ __align__(16) __nv_bfloat16 g_al[Mtot * Cc];
__device__ __align__(16) __nv_bfloat16 g_wsh[Cc * Cc];   // W^T (n-major, k contig)
__device__ __align__(16) __nv_bfloat16 g_wsl[Cc * Cc];
__device__ __align__(16) __nv_bfloat16 g_wnh[Cc * Cc];
__device__ __align__(16) __nv_bfloat16 g_wnl[Cc * Cc];
__device__ __align__(16) float g_part[Mtot * Cc];        // x-half partial sums

__device__ __forceinline__ int load_idx(const unsigned* w, int pos) {
    int v = g_is64 ? (int)w[2 * pos] : (int)w[pos];
    return v & (Nn - 1);
}

// ---------------- 1. zero counters + detect edge dtype (fused) ---------------
__global__ void init_k(const unsigned* __restrict__ w) {
    if (blockIdx.x < 32) {
        int i = blockIdx.x * 256 + threadIdx.x;
        g_deg[i] = 0; g_cur[i] = 0;
    } else {
        int nz = (w[2 * threadIdx.x + 1] != 0u);
        int total = __syncthreads_count(nz);
        if (threadIdx.x == 0) g_is64 = (total == 0) ? 1 : 0;
    }
}

// ---------------- 2. degree counting ----------------------------------------
__global__ void count_k(const unsigned* __restrict__ w) {
    int e = blockIdx.x * blockDim.x + threadIdx.x;
    if (e < Ee) atomicAdd(&g_deg[load_idx(w, e)], 1);
}

// ---------------- 3. exclusive scan (coalesced, 256 threads) ----------------
#define SPAD(i) ((i) + ((i) >> 5))
__global__ void scan_k() {
    __shared__ int s[Nn + Nn / 32];     // padded, conflict-free
    __shared__ int wsum[8], wexc[8];
    int tid = threadIdx.x;
    const int4* g4 = (const int4*)g_deg;
    for (int i = tid; i < Nn / 4; i += 256) {
        int4 q = g4[i];
        int b = i * 4;
        s[SPAD(b)] = q.x; s[SPAD(b + 1)] = q.y; s[SPAD(b + 2)] = q.z; s[SPAD(b + 3)] = q.w;
    }
    __syncthreads();
    int v[32]; int sum = 0;
#pragma unroll
    for (int k = 0; k < 32; k++) { v[k] = s[SPAD(tid * 32 + k)]; sum += v[k]; }
    int incl = sum;
#pragma unroll
    for (int d = 1; d < 32; d <<= 1) {
        int t = __shfl_up_sync(0xFFFFFFFFu, incl, d);
        if ((tid & 31) >= d) incl += t;
    }
    if ((tid & 31) == 31) wsum[tid >> 5] = incl;
    __syncthreads();
    if (tid < 8) {
        int e = 0;
        for (int q = 0; q < tid; q++) e += wsum[q];
        wexc[tid] = e;
    }
    __syncthreads();
    int excl = wexc[tid >> 5] + incl - sum;
    // stage exclusive offsets, write out coalesced
    int ex = excl;
#pragma unroll
    for (int k = 0; k < 32; k++) { s[SPAD(tid * 32 + k)] = ex; ex += v[k]; }
    __syncthreads();
    int4* o4 = (int4*)g_off;
    for (int i = tid; i < Nn / 4; i += 256) {
        int b = i * 4;
        o4[i] = make_int4(s[SPAD(b)], s[SPAD(b + 1)], s[SPAD(b + 2)], s[SPAD(b + 3)]);
    }
    if (tid == 255) g_off[Nn] = ex;
    __syncthreads();
    // stage 1/deg as float bits, write out coalesced
#pragma unroll
    for (int k = 0; k < 32; k++)
        s[SPAD(tid * 32 + k)] = __float_as_int(1.0f / (float)(v[k] + 1));
    __syncthreads();
    float4* f4 = (float4*)g_invdeg;
    for (int i = tid; i < Nn / 4; i += 256) {
        int b = i * 4;
        f4[i] = make_float4(__int_as_float(s[SPAD(b)]),     __int_as_float(s[SPAD(b + 1)]),
                            __int_as_float(s[SPAD(b + 2)]), __int_as_float(s[SPAD(b + 3)]));
    }
}

// ---------------- 4. CSR fill ------------------------------------------------
__global__ void fill_k(const unsigned* __restrict__ w) {
    int e = blockIdx.x * blockDim.x + threadIdx.x;
    if (e < Ee) {
        int src = load_idx(w, e);
        int dst = load_idx(w, Ee + e);
        int p = atomicAdd(&g_cur[src], 1);
        g_col[g_off[src] + p] = dst;
    }
}

// ---------------- 5. x split + weight transpose/split (fused) ----------------
__global__ __launch_bounds__(256) void split_k(
    const float* __restrict__ x,
    const float* __restrict__ Ws, const float* __restrict__ Wn)
{
    if (blockIdx.x < 8192) {
        size_t t = (size_t)blockIdx.x * 256 + threadIdx.x;   // float4 index
        float4 v = *(const float4*)(x + t * 4);
        float f[4] = {v.x, v.y, v.z, v.w};
        ushort4 hi, lo;
        unsigned short* hp = &hi.x; unsigned short* lp = &lo.x;
#pragma unroll
        for (int q = 0; q < 4; q++) {
            __nv_bfloat16 h = __float2bfloat16(f[q]);
            hp[q] = __bfloat16_as_ushort(h);
            lp[q] = __bfloat16_as_ushort(__float2bfloat16(f[q] - __bfloat162float(h)));
        }
        *(ushort4*)(g_xh + t * 4) = hi;
        *(ushort4*)(g_xl + t * 4) = lo;
    } else {
        int n = blockIdx.x - 8192, k = threadIdx.x;
        float a = Ws[k * Cc + n];
        __nv_bfloat16 h = __float2bfloat16(a);
        g_wsh[n * Cc + k] = h;
        g_wsl[n * Cc + k] = __float2bfloat16(a - __bfloat162float(h));
        float b = Wn[k * Cc + n];
        __nv_bfloat16 h2 = __float2bfloat16(b);
        g_wnh[n * Cc + k] = h2;
        g_wnl[n * Cc + k] = __float2bfloat16(b - __bfloat162float(h2));
    }
}

// ---------------- shared GEMM core (12 k64-chunks, 3 terms) ------------------
// CTA 128(M) x 128(N), 8 warps, warp tile 64x32, double-buffered cp.async.
#define ROWB   144
#define TILE_B (128 * ROWB)
#define STG_B  (2 * TILE_B)
#define GSMEM  (2 * STG_B)      // 73728 B

template<int PHASE>
__device__ __forceinline__ void gemm_body(
    int gid, char* smem,
    const float* bs, const float* bn, float* out)
{
    uint32_t sb = smem_u32(smem);
    int tid = threadIdx.x, lane = tid & 31, wid = tid >> 5;
    int m0 = (gid & 255) * 128, n0 = (gid >> 8) * 128;
    int wm = (wid >> 2) * 64, wn = (wid & 3) * 32;

    float acc[4][4][4] = {};

    auto load_tile = [&](int it, int buf) {
        int term = it >> 2, kc = (it & 3) * 64;
        const __nv_bfloat16* A = (PHASE == 1)
            ? (term == 0 ? g_xh : term == 1 ? g_xl : g_xh)
            : (term == 0 ? g_ah : term == 1 ? g_al : g_ah);
        const __nv_bfloat16* B = (PHASE == 1)
            ? (term == 2 ? g_wsl : g_wsh)
            : (term == 2 ? g_wnl : g_wnh);
        uint32_t ab = sb + buf * STG_B;
        uint32_t bb = ab + TILE_B;
#pragma unroll
        for (int c = 0; c < 4; c++) {
            int id = tid + 256 * c, row = id >> 3, ch = id & 7;
            CP_ASYNC16(ab + row * ROWB + ch * 16,
                       A + (size_t)(m0 + row) * Cc + kc + ch * 8);
            CP_ASYNC16(bb + row * ROWB + ch * 16,
                       B + (size_t)(n0 + row) * Cc + kc + ch * 8);
        }
        CP_COMMIT();
    };

    load_tile(0, 0);
    load_tile(1, 1);

    for (int it = 0; it < 12; it++) {
        int buf = it & 1;
        if (it < 10) CP_WAIT1(); else CP_WAIT0();
        __syncthreads();

        uint32_t ab = sb + buf * STG_B;
        uint32_t bb = ab + TILE_B;
        uint32_t a_l = ab + (wm + (lane & 15)) * ROWB + (lane >> 4) * 16;
        uint32_t b_l = bb + (wn + (lane & 7) + ((lane >> 4) & 1) * 8) * ROWB
                          + ((lane >> 3) & 1) * 16;
#pragma unroll
        for (int s = 0; s < 4; s++) {
            uint32_t ar[4][4];
#pragma unroll
            for (int i = 0; i < 4; i++)
                LDSM_X4(ar[i][0], ar[i][1], ar[i][2], ar[i][3],
                        a_l + i * 16 * ROWB + s * 32);
            uint32_t br[2][4];
#pragma unroll
            for (int j = 0; j < 2; j++)
                LDSM_X4(br[j][0], br[j][1], br[j][2], br[j][3],
                        b_l + j * 16 * ROWB + s * 32);
#pragma unroll
            for (int i = 0; i < 4; i++)
#pragma unroll
                for (int jn = 0; jn < 4; jn++)
                    MMA_BF16(acc[i][jn], ar[i],
                             br[jn >> 1][(jn & 1) * 2],
                             br[jn >> 1][(jn & 1) * 2 + 1]);
        }
        __syncthreads();
        if (it + 2 < 12) load_tile(it + 2, buf);
    }

    int g = lane >> 2, tig = lane & 3;
#pragma unroll
    for (int jn = 0; jn < 4; jn++) {
        int n = n0 + wn + jn * 8 + tig * 2;
        float b0 = 0.f, b1 = 0.f;
        if (PHASE == 2) { b0 = bs[n] + bn[n]; b1 = bs[n + 1] + bn[n + 1]; }
#pragma unroll
        for (int i = 0; i < 4; i++) {
            int m = m0 + wm + i * 16 + g;
            if (PHASE == 1) {
                *(float2*)(g_part + (size_t)m * Cc + n) =
                    make_float2(acc[i][jn][0], acc[i][jn][1]);
                *(float2*)(g_part + (size_t)(m + 8) * Cc + n) =
                    make_float2(acc[i][jn][2], acc[i][jn][3]);
            } else {
                float2 p0 = *(const float2*)(g_part + (size_t)m * Cc + n);
                *(float2*)(out + (size_t)m * Cc + n) =
                    make_float2(gelu_f(acc[i][jn][0] + p0.x + b0),
                                gelu_f(acc[i][jn][1] + p0.y + b1));
                float2 p1 = *(const float2*)(g_part + (size_t)(m + 8) * Cc + n);
                *(float2*)(out + (size_t)(m + 8) * Cc + n) =
                    make_float2(gelu_f(acc[i][jn][2] + p1.x + b0),
                                gelu_f(acc[i][jn][3] + p1.y + b1));
            }
        }
    }
}

// ---------------- 6. fused: aggregation (16/17 blocks) + x-GEMM (1/17) -------
__global__ __launch_bounds__(256, 2) void fused1_k(const float* __restrict__ x)
{
    extern __shared__ __align__(128) char smem[];
    int b = blockIdx.x;
    int grp = b / 17, r = b - grp * 17;

    if (r == 16) {          // gemm phase-1 tile (x-half -> g_part)
        gemm_body<1>(grp, smem, 0, 0, 0);
        return;
    }
    // aggregation for node i
    int i   = grp * 16 + r;
    int tid = threadIdx.x;
    int bq  = tid >> 6;
    int cg  = (tid & 63) << 2;
    const float* xb = x + (size_t)bq * NC;

    float4 acc = *(const float4*)(xb + (size_t)i * Cc + cg);   // self loop
    int s = g_off[i], e = g_off[i + 1];

    __shared__ int nb[256];
    for (int base = s; base < e; base += 256) {
        int cnt = min(256, e - base);
        __syncthreads();
        if (tid < cnt) nb[tid] = g_col[base + tid];
        __syncthreads();
#pragma unroll 8
        for (int k = 0; k < cnt; k++) {
            const float4 v = *(const float4*)(xb + (size_t)nb[k] * Cc + cg);
            acc.x += v.x; acc.y += v.y; acc.z += v.z; acc.w += v.w;
        }
    }
    float wgt = g_invdeg[i];
    float f[4] = {acc.x * wgt, acc.y * wgt, acc.z * wgt, acc.w * wgt};
    ushort4 hi, lo;
    unsigned short* hp = &hi.x; unsigned short* lp = &lo.x;
#pragma unroll
    for (int q = 0; q < 4; q++) {
        __nv_bfloat16 h = __float2bfloat16(f[q]);
        hp[q] = __bfloat16_as_ushort(h);
        lp[q] = __bfloat16_as_ushort(__float2bfloat16(f[q] - __bfloat162float(h)));
    }
    size_t o = (size_t)bq * NC + (size_t)i * Cc + cg;
    *(ushort4*)(g_ah + o) = hi;
    *(ushort4*)(g_al + o) = lo;
}

// ---------------- 7. gemm phase-2 (agg-half + partial + bias + GELU) ---------
__global__ __launch_bounds__(256, 2) void gemm2_k(
    const float* __restrict__ bs, const float* __restrict__ bn,
    float* __restrict__ out)
{
    extern __shared__ __align__(128) char smem[];
    gemm_body<2>(blockIdx.x, smem, bs, bn, out);
}

// ---------------- launch -----------------------------------------------------
extern "C" void kernel_launch(void* const* d_in, const int* in_sizes, int n_in,
                              void* d_out, int out_size)
{
    const float* x = 0; const unsigned* ei = 0;
    const float* Ws = 0; const float* bsv = 0;
    const float* Wn = 0; const float* bnv = 0;
    for (int i = 0; i < n_in; i++) {
        int sz = in_sizes[i];
        if (sz == Bq * NC)                      x  = (const float*)d_in[i];
        else if (sz == 2 * Ee || sz == 4 * Ee)  ei = (const unsigned*)d_in[i];
        else if (sz == Cc * Cc) { if (!Ws) Ws = (const float*)d_in[i]; else Wn = (const float*)d_in[i]; }
        else if (sz == Cc)      { if (!bsv) bsv = (const float*)d_in[i]; else bnv = (const float*)d_in[i]; }
    }
    float* out = (float*)d_out;

    static int smem_set = 0;
    if (!smem_set) {
        cudaFuncSetAttribute(fused1_k, cudaFuncAttributeMaxDynamicSharedMemorySize, GSMEM);
        cudaFuncSetAttribute(gemm2_k,  cudaFuncAttributeMaxDynamicSharedMemorySize, GSMEM);
        smem_set = 1;
    }

    init_k  <<<33, 256>>>(ei);
    count_k <<<Ee / 256, 256>>>(ei);
    scan_k  <<<1, 256>>>();
    fill_k  <<<Ee / 256, 256>>>(ei);
    split_k <<<8448, 256>>>(x, Ws, Wn);
    fused1_k<<<17 * 512, 256, GSMEM>>>(x);
    gemm2_k <<<512, 256, GSMEM>>>(bsv, bnv, out);
}